// round 2
// baseline (speedup 1.0000x reference)
#include <cuda_runtime.h>

#define NN 10000
#define NE 160000
#define INV3 0.5773502691896258f
#define SKN  0.03952847075210474f      /* 1/sqrt(640) */
#define LN   0.0027621358640099513f    /* 1/sqrt(128)/32 */

__device__ float g_x0u[NN * 64];
__device__ float g_x1u[3][NN * 64];
__device__ float g_scs[NN * 128];
__device__ float g_scv[NN * 192];
__device__ float g_tw[(size_t)NE * 256];
__device__ int g_cnt[NN], g_row[NN + 1], g_cur[NN], g_csr[NE];

__device__ __forceinline__ float silu_f(float x) { return x / (1.0f + __expf(-x)); }

// ================= K1: up-projection + skip connections =================
__global__ void __launch_bounds__(256) node_prep(
    const float* __restrict__ attrs, const float* __restrict__ feats,
    const float* __restrict__ Wup0, const float* __restrict__ Wup1,
    const float* __restrict__ Wsks, const float* __restrict__ Wskv)
{
    __shared__ float sx0[32 * 65];
    __shared__ float sx1[32 * 193];
    __shared__ float sat[32 * 11];
    const int t = threadIdx.x;
    const int n0 = blockIdx.x * 32;

    for (int idx = t; idx < 32 * 256; idx += 256) {
        int m = idx >> 8, c = idx & 255;
        int n = n0 + m;
        float v = (n < NN) ? feats[(size_t)n * 256 + c] : 0.f;
        if (c < 64) sx0[m * 65 + c] = v; else sx1[m * 193 + (c - 64)] = v;
    }
    for (int idx = t; idx < 32 * 10; idx += 256) {
        int m = idx / 10, a = idx - m * 10;
        int n = n0 + m;
        sat[m * 11 + a] = (n < NN) ? attrs[n * 10 + a] : 0.f;
    }
    __syncthreads();

    // ---- up projections ----
    {
        const int v = t & 63, mg = t >> 6;
        float a0[8], a1[8][3];
        #pragma unroll
        for (int j = 0; j < 8; j++) { a0[j] = 0.f; a1[j][0] = a1[j][1] = a1[j][2] = 0.f; }
        for (int u = 0; u < 64; u++) {
            float w0 = Wup0[u * 64 + v];
            float w1 = Wup1[u * 64 + v];
            #pragma unroll
            for (int j = 0; j < 8; j++) {
                int m = mg * 8 + j;
                a0[j] += sx0[m * 65 + u] * w0;
                const float* xv = &sx1[m * 193 + u * 3];
                a1[j][0] += xv[0] * w1;
                a1[j][1] += xv[1] * w1;
                a1[j][2] += xv[2] * w1;
            }
        }
        #pragma unroll
        for (int j = 0; j < 8; j++) {
            int n = n0 + mg * 8 + j;
            if (n < NN) {
                g_x0u[n * 64 + v] = a0[j] * 0.125f;
                g_x1u[0][n * 64 + v] = a1[j][0] * 0.125f;
                g_x1u[1][n * 64 + v] = a1[j][1] * 0.125f;
                g_x1u[2][n * 64 + v] = a1[j][2] * 0.125f;
            }
        }
    }

    // ---- sc_s: einsum('nu,na,uav->nv') ----
    {
        const int gv = t & 31, gm = t >> 5;
        float acc[4][4];
        #pragma unroll
        for (int j = 0; j < 4; j++) { acc[j][0] = acc[j][1] = acc[j][2] = acc[j][3] = 0.f; }
        for (int u = 0; u < 64; u++) {
            float xj[4];
            #pragma unroll
            for (int j = 0; j < 4; j++) xj[j] = sx0[(gm * 4 + j) * 65 + u];
            #pragma unroll
            for (int a = 0; a < 10; a++) {
                float4 b = *reinterpret_cast<const float4*>(&Wsks[(u * 10 + a) * 128 + gv * 4]);
                #pragma unroll
                for (int j = 0; j < 4; j++) {
                    float p = xj[j] * sat[(gm * 4 + j) * 11 + a];
                    acc[j][0] += p * b.x; acc[j][1] += p * b.y;
                    acc[j][2] += p * b.z; acc[j][3] += p * b.w;
                }
            }
        }
        #pragma unroll
        for (int j = 0; j < 4; j++) {
            int n = n0 + gm * 4 + j;
            if (n < NN) {
                #pragma unroll
                for (int l = 0; l < 4; l++) g_scs[n * 128 + gv * 4 + l] = acc[j][l] * SKN;
            }
        }
    }

    // ---- sc_v: einsum('nui,na,uav->nvi') ----
    {
        const int gv = t & 31, gm = t >> 5;
        float acc[4][3][2];
        #pragma unroll
        for (int j = 0; j < 4; j++)
            #pragma unroll
            for (int i = 0; i < 3; i++) { acc[j][i][0] = 0.f; acc[j][i][1] = 0.f; }
        for (int u = 0; u < 64; u++) {
            float xv[4][3];
            #pragma unroll
            for (int j = 0; j < 4; j++) {
                const float* p = &sx1[(gm * 4 + j) * 193 + u * 3];
                xv[j][0] = p[0]; xv[j][1] = p[1]; xv[j][2] = p[2];
            }
            #pragma unroll
            for (int a = 0; a < 10; a++) {
                float2 b = *reinterpret_cast<const float2*>(&Wskv[(u * 10 + a) * 64 + gv * 2]);
                #pragma unroll
                for (int j = 0; j < 4; j++) {
                    float pa = sat[(gm * 4 + j) * 11 + a];
                    #pragma unroll
                    for (int i = 0; i < 3; i++) {
                        float p = xv[j][i] * pa;
                        acc[j][i][0] += p * b.x;
                        acc[j][i][1] += p * b.y;
                    }
                }
            }
        }
        #pragma unroll
        for (int j = 0; j < 4; j++) {
            int n = n0 + gm * 4 + j;
            if (n < NN) {
                #pragma unroll
                for (int i = 0; i < 3; i++) {
                    g_scv[n * 192 + (gv * 2 + 0) * 3 + i] = acc[j][i][0] * SKN;
                    g_scv[n * 192 + (gv * 2 + 1) * 3 + i] = acc[j][i][1] * SKN;
                }
            }
        }
    }
}

// ================= CSR build =================
__global__ void zero_k() {
    int i = blockIdx.x * blockDim.x + threadIdx.x;
    if (i < NN) g_cnt[i] = 0;
}
__global__ void hist_k(const int* __restrict__ ei) {
    int e = blockIdx.x * blockDim.x + threadIdx.x;
    if (e < NE) atomicAdd(&g_cnt[ei[NE + e]], 1);
}
__global__ void __launch_bounds__(1024) scan_k() {
    __shared__ int ssum[1024];
    int t = threadIdx.x;
    int base = t * 10, s = 0;
    #pragma unroll
    for (int i = 0; i < 10; i++) { int idx = base + i; if (idx < NN) s += g_cnt[idx]; }
    ssum[t] = s;
    __syncthreads();
    for (int off = 1; off < 1024; off <<= 1) {
        int v = ssum[t];
        int add = (t >= off) ? ssum[t - off] : 0;
        __syncthreads();
        ssum[t] = v + add;
        __syncthreads();
    }
    int run = (t == 0) ? 0 : ssum[t - 1];
    for (int i = 0; i < 10; i++) {
        int idx = base + i;
        if (idx < NN) { g_row[idx] = run; g_cur[idx] = run; run += g_cnt[idx]; }
    }
    if (t == 1023) g_row[NN] = ssum[1023];
}
__global__ void fill_k(const int* __restrict__ ei) {
    int e = blockIdx.x * blockDim.x + threadIdx.x;
    if (e < NE) {
        int pos = atomicAdd(&g_cur[ei[NE + e]], 1);
        g_csr[pos] = e;
    }
}
__global__ void sort_k() {
    int n = blockIdx.x * blockDim.x + threadIdx.x;
    if (n < NN) {
        int b = g_row[n], e = g_row[n + 1];
        for (int i = b + 1; i < e; i++) {
            int v = g_csr[i], j = i - 1;
            while (j >= b && g_csr[j] > v) { g_csr[j + 1] = g_csr[j]; j--; }
            g_csr[j + 1] = v;
        }
    }
}

// ================= K2: fused edge MLP =================
__device__ __forceinline__ void layer64(const float* __restrict__ hin,
                                        const float* __restrict__ W,
                                        float* __restrict__ hout, int t)
{
    int gv = t & 15, ge = t >> 4;
    float acc[4][4];
    #pragma unroll
    for (int j = 0; j < 4; j++) { acc[j][0] = acc[j][1] = acc[j][2] = acc[j][3] = 0.f; }
    #pragma unroll 4
    for (int k = 0; k < 64; k++) {
        float4 b = *reinterpret_cast<const float4*>(&W[k * 64 + gv * 4]);
        #pragma unroll
        for (int j = 0; j < 4; j++) {
            float a = hin[(ge * 4 + j) * 65 + k];
            acc[j][0] += a * b.x; acc[j][1] += a * b.y;
            acc[j][2] += a * b.z; acc[j][3] += a * b.w;
        }
    }
    #pragma unroll
    for (int j = 0; j < 4; j++)
        #pragma unroll
        for (int l = 0; l < 4; l++)
            hout[(ge * 4 + j) * 65 + gv * 4 + l] = silu_f(acc[j][l] * 0.125f);
}

__global__ void __launch_bounds__(256) edge_mlp(
    const float* __restrict__ ef, const float* __restrict__ M1,
    const float* __restrict__ M2, const float* __restrict__ M3,
    const float* __restrict__ M4)
{
    __shared__ float ef_s[64 * 9];
    __shared__ float ha[64 * 65];
    __shared__ float hb[64 * 65];
    const int t = threadIdx.x;
    const int e0 = blockIdx.x * 64;

    for (int idx = t; idx < 64 * 8; idx += 256) {
        int m = idx >> 3, k = idx & 7;
        ef_s[m * 9 + k] = ef[(size_t)(e0 + m) * 8 + k];
    }
    __syncthreads();

    // layer 1 (k=8)
    {
        int gv = t & 15, ge = t >> 4;
        float acc[4][4];
        #pragma unroll
        for (int j = 0; j < 4; j++) { acc[j][0] = acc[j][1] = acc[j][2] = acc[j][3] = 0.f; }
        #pragma unroll
        for (int k = 0; k < 8; k++) {
            float4 b = *reinterpret_cast<const float4*>(&M1[k * 64 + gv * 4]);
            #pragma unroll
            for (int j = 0; j < 4; j++) {
                float a = ef_s[(ge * 4 + j) * 9 + k];
                acc[j][0] += a * b.x; acc[j][1] += a * b.y;
                acc[j][2] += a * b.z; acc[j][3] += a * b.w;
            }
        }
        #pragma unroll
        for (int j = 0; j < 4; j++)
            #pragma unroll
            for (int l = 0; l < 4; l++)
                ha[(ge * 4 + j) * 65 + gv * 4 + l] = silu_f(acc[j][l] * 0.35355339059327373f);
    }
    __syncthreads();
    layer64(ha, M2, hb, t);
    __syncthreads();
    layer64(hb, M3, ha, t);
    __syncthreads();

    // output layer (256 wide, no silu)
    {
        int ce = t & 63, eg = t >> 6;
        #pragma unroll
        for (int rep = 0; rep < 4; rep++) {
            int eb = (rep * 4 + eg) * 4;
            float acc[4][4];
            #pragma unroll
            for (int j = 0; j < 4; j++) { acc[j][0] = acc[j][1] = acc[j][2] = acc[j][3] = 0.f; }
            #pragma unroll 4
            for (int k = 0; k < 64; k++) {
                float4 b = *reinterpret_cast<const float4*>(&M4[k * 256 + ce * 4]);
                #pragma unroll
                for (int j = 0; j < 4; j++) {
                    float a = ha[(eb + j) * 65 + k];
                    acc[j][0] += a * b.x; acc[j][1] += a * b.y;
                    acc[j][2] += a * b.z; acc[j][3] += a * b.w;
                }
            }
            #pragma unroll
            for (int j = 0; j < 4; j++) {
                float4 o = make_float4(acc[j][0] * 0.125f, acc[j][1] * 0.125f,
                                       acc[j][2] * 0.125f, acc[j][3] * 0.125f);
                *reinterpret_cast<float4*>(&g_tw[(size_t)(e0 + eb + j) * 256 + ce * 4]) = o;
            }
        }
    }
}

// ================= K4: gather + linear + gate + output =================
__global__ void __launch_bounds__(256) gather_final(
    const int* __restrict__ ei, const float* __restrict__ ear,
    const float* __restrict__ eai, const float* __restrict__ Wls,
    const float* __restrict__ Wlv, float* __restrict__ out)
{
    __shared__ float2 s_ms[4][128];
    __shared__ float2 s_mv[4][128][3];
    const int t = threadIdx.x;
    const int g = t >> 6, v = t & 63;
    const int n = blockIdx.x * 4 + g;

    float msr0 = 0.f, msr1 = 0.f, msi0 = 0.f, msi1 = 0.f;
    float mvr0[3] = {0.f, 0.f, 0.f}, mvr1[3] = {0.f, 0.f, 0.f};
    float mvi0[3] = {0.f, 0.f, 0.f}, mvi1[3] = {0.f, 0.f, 0.f};

    if (n < NN) {
        int b = g_row[n], ed = g_row[n + 1];
        for (int idx = b; idx < ed; idx++) {
            int e = g_csr[idx];
            int s = ei[e];
            float y0r = ear[e * 4], y1r0 = ear[e * 4 + 1], y1r1 = ear[e * 4 + 2], y1r2 = ear[e * 4 + 3];
            float y0i = eai[e * 4], y1i0 = eai[e * 4 + 1], y1i1 = eai[e * 4 + 2], y1i2 = eai[e * 4 + 3];
            float x0 = g_x0u[s * 64 + v];
            float x10 = g_x1u[0][s * 64 + v];
            float x11 = g_x1u[1][s * 64 + v];
            float x12 = g_x1u[2][s * 64 + v];
            const float* twp = &g_tw[(size_t)e * 256];
            float wA = twp[v], wB = twp[64 + v], wC = twp[128 + v], wD = twp[192 + v];

            float dr = x10 * y1r0 + x11 * y1r1 + x12 * y1r2;
            float di = x10 * y1i0 + x11 * y1i1 + x12 * y1i2;
            msr0 += x0 * y0r * wA;
            msi0 += x0 * y0i * wA;
            msr1 += dr * INV3 * wD;
            msi1 += di * INV3 * wD;
            float xb = x0 * wB;
            mvr0[0] += xb * y1r0; mvr0[1] += xb * y1r1; mvr0[2] += xb * y1r2;
            mvi0[0] += xb * y1i0; mvi0[1] += xb * y1i1; mvi0[2] += xb * y1i2;
            float tcr = y0r * wC, tci = y0i * wC;
            mvr1[0] += x10 * tcr; mvr1[1] += x11 * tcr; mvr1[2] += x12 * tcr;
            mvi1[0] += x10 * tci; mvi1[1] += x11 * tci; mvi1[2] += x12 * tci;
        }
    }
    s_ms[g][v] = make_float2(msr0, msi0);
    s_ms[g][64 + v] = make_float2(msr1, msi1);
    #pragma unroll
    for (int i = 0; i < 3; i++) {
        s_mv[g][v][i] = make_float2(mvr0[i], mvi0[i]);
        s_mv[g][64 + v][i] = make_float2(mvr1[i], mvi1[i]);
    }
    __syncthreads();

    float lsr0 = 0.f, lsr1 = 0.f, lsi0 = 0.f, lsi1 = 0.f;
    float lvr[3] = {0.f, 0.f, 0.f}, lvi[3] = {0.f, 0.f, 0.f};
    #pragma unroll 4
    for (int u = 0; u < 128; u++) {
        float wa = Wls[u * 128 + v];
        float wb = Wls[u * 128 + 64 + v];
        float wv = Wlv[u * 64 + v];
        float2 m = s_ms[g][u];
        lsr0 += m.x * wa; lsr1 += m.x * wb;
        lsi0 += m.y * wa; lsi1 += m.y * wb;
        #pragma unroll
        for (int i = 0; i < 3; i++) {
            float2 mv = s_mv[g][u][i];
            lvr[i] += mv.x * wv;
            lvi[i] += mv.y * wv;
        }
    }

    if (n < NN) {
        float sr0 = lsr0 * LN + g_scs[n * 128 + v];
        float sr1 = lsr1 * LN + g_scs[n * 128 + 64 + v];
        float scal_r = silu_f(sr0);
        float gr = silu_f(sr1);
        float scal_i = silu_f(lsi0 * LN);
        float gi = silu_f(lsi1 * LN);
        float* o = out + (size_t)n * 512;
        o[v * 2 + 0] = scal_r;
        o[v * 2 + 1] = scal_i;
        #pragma unroll
        for (int i = 0; i < 3; i++) {
            float vr = (lvr[i] * LN + g_scv[n * 192 + v * 3 + i]) * gr;
            float vi = (lvi[i] * LN) * gi;
            int k = 64 + v * 3 + i;
            o[k * 2 + 0] = vr;
            o[k * 2 + 1] = vi;
        }
    }
}

// ================= launch =================
extern "C" void kernel_launch(void* const* d_in, const int* in_sizes, int n_in,
                              void* d_out, int out_size)
{
    const float* node_attrs = (const float*)d_in[0];
    const float* node_feats = (const float*)d_in[1];
    const float* ear        = (const float*)d_in[2];
    const float* eai        = (const float*)d_in[3];
    const float* ef         = (const float*)d_in[4];
    const float* Wup0       = (const float*)d_in[5];
    const float* Wup1       = (const float*)d_in[6];
    const float* M1         = (const float*)d_in[7];
    const float* M2         = (const float*)d_in[8];
    const float* M3         = (const float*)d_in[9];
    const float* M4         = (const float*)d_in[10];
    const float* Wls        = (const float*)d_in[11];
    const float* Wlv        = (const float*)d_in[12];
    const float* Wsks       = (const float*)d_in[13];
    const float* Wskv       = (const float*)d_in[14];
    const int*   ei         = (const int*)d_in[15];
    float* out = (float*)d_out;

    node_prep<<<(NN + 31) / 32, 256>>>(node_attrs, node_feats, Wup0, Wup1, Wsks, Wskv);
    zero_k<<<(NN + 255) / 256, 256>>>();
    hist_k<<<(NE + 255) / 256, 256>>>(ei);
    scan_k<<<1, 1024>>>();
    fill_k<<<(NE + 255) / 256, 256>>>(ei);
    sort_k<<<(NN + 127) / 128, 128>>>();
    edge_mlp<<<NE / 64, 256>>>(ef, M1, M2, M3, M4);
    gather_final<<<(NN + 3) / 4, 256>>>(ei, ear, eai, Wls, Wlv, out);
}